// round 15
// baseline (speedup 1.0000x reference)
#include <cuda_runtime.h>
#include <cuda_fp16.h>
#include <cstdint>

// ---------------------------------------------------------------------------
// NNConv fused pipeline, fp16 mma.sync (legacy tensor path).
//   K_pre:   w2 transpose (258 blk) + KA edge-MLP (128 blk) + zeroing (160 blk)
//   K_fused: [phase 1] KB msg GEMM, K=128 chunks, balanced over 148 CTAs
//            (1 CTA/SM, all co-resident)  -> grid-wide barrier ->
//            [phase 2] KC: out = x + gelu(seg/cnt + x@root + bias),
//            157 node-tiles strided over the same 148 CTAs (seg L2-hot).
// ---------------------------------------------------------------------------

#define N_NODES 10000
#define N_EDGES 16384
#define DD      128
#define W2HN    ((DD + 1) * 16384)
#define NTILES  (N_EDGES / 128)
#define NCH_PT  129
#define NCH_TOT (NTILES * NCH_PT)        // 16512
#define KB_GRID 148
#define KC_TILES ((N_NODES + 63) / 64)   // 157

__device__ float  g_h[N_EDGES * DD];
__device__ __half g_w2h[W2HN];           // [k][ih][o][il]
__device__ float  g_seg[N_NODES * DD];
__device__ int    g_cnt[N_NODES + 16];
__device__ int    g_is64;
__device__ unsigned g_bar;

// ---------------- helpers ----------------

__device__ __forceinline__ int load_idx(const void* ei, int pos) {
    if (g_is64) return (int)((const long long*)ei)[pos];
    return ((const int*)ei)[pos];
}

__device__ __forceinline__ void cp_async16(void* smem_dst, const void* gsrc) {
    unsigned saddr = (unsigned)__cvta_generic_to_shared(smem_dst);
    asm volatile("cp.async.cg.shared.global [%0], [%1], 16;\n" ::"r"(saddr), "l"(gsrc));
}
#define CP_COMMIT() asm volatile("cp.async.commit_group;\n")
#define CP_WAIT1()  asm volatile("cp.async.wait_group 1;\n")
#define CP_WAIT0()  asm volatile("cp.async.wait_group 0;\n")

#define MMA_F16(C, A, B0, B1)                                                   \
    asm volatile(                                                               \
        "mma.sync.aligned.m16n8k16.row.col.f32.f16.f16.f32 "                    \
        "{%0,%1,%2,%3}, {%4,%5,%6,%7}, {%8,%9}, {%0,%1,%2,%3};\n"               \
        : "+f"((C)[0]), "+f"((C)[1]), "+f"((C)[2]), "+f"((C)[3])                \
        : "r"((A)[0]), "r"((A)[1]), "r"((A)[2]), "r"((A)[3]),                   \
          "r"((B0)), "r"((B1)))

__device__ __forceinline__ unsigned pack_h2(float a, float b) {
    unsigned u;
    asm("cvt.rn.f16x2.f32 %0, %2, %1;" : "=r"(u) : "f"(a), "f"(b));
    return u;
}

// ---------------- K_pre: transpose(258) + KA(128) + zeroing(160) ------------

#define INIT_ZBLK 160
#define PRE_GRID  (258 + 128 + INIT_ZBLK)

#define KA_EA_OFF  0
#define KA_W1_OFF  (128 * 136 * 2)
#define KA_B1_OFF  (2 * 128 * 136 * 2)
#define SMEM_PRE   (KA_B1_OFF + 512 + 256)

__global__ __launch_bounds__(256) void k_pre(
    const float* __restrict__ w2, const float* __restrict__ b2,
    const void* __restrict__ ei,
    const float* __restrict__ ea, const float* __restrict__ w1,
    const float* __restrict__ b1)
{
    extern __shared__ char smP[];
    const int b = blockIdx.x;
    const int tid = threadIdx.x;

    if (b < 258) {
        if (b == 0 && tid < 32) {
            const int* e32 = (const int*)ei;
            int nz = 0;
            for (int i = tid; i < 2048; i += 32) nz |= e32[2 * i + 1];
            unsigned any = __ballot_sync(0xffffffffu, nz != 0);
            if (tid == 0) g_is64 = (any == 0u) ? 1 : 0;
        }
        if (b == 0 && tid == 32) g_bar = 0u;   // reset grid barrier each call
        __half* ts = (__half*)smP;              // [64][136]
        const int k = b >> 1, ih = b & 1;
        const float* src = ((k < DD) ? (w2 + (size_t)k * 16384) : b2) + ih * 64 * 128;
#pragma unroll
        for (int j = 0; j < 8; j++) {
            int idx = tid + j * 256;
            int ii = idx >> 5, o4 = (idx & 31) * 4;
            float4 v = *(const float4*)(src + ii * 128 + o4);
            __half2* d = (__half2*)(ts + ii * 136 + o4);
            d[0] = __floats2half2_rn(v.x, v.y);
            d[1] = __floats2half2_rn(v.z, v.w);
        }
        __syncthreads();
#pragma unroll
        for (int j = 0; j < 4; j++) {
            int idx = tid + j * 256;
            int o = idx >> 3, il8 = (idx & 7) * 8;
            __half tmp[8];
#pragma unroll
            for (int q = 0; q < 8; q++) tmp[q] = ts[(il8 + q) * 136 + o];
            *(uint4*)(g_w2h + (size_t)k * 16384 + ih * 8192 + o * 64 + il8) =
                *(uint4*)tmp;
        }
    } else if (b < 386) {
        __half* EAs = (__half*)(smP + KA_EA_OFF);
        __half* W1T = (__half*)(smP + KA_W1_OFF);
        float*  b1s = (float*)(smP + KA_B1_OFF);
        const int e0 = (b - 258) * 128;

#pragma unroll
        for (int j = 0; j < 16; j++) {
            int idx = tid + j * 256;
            int r = idx >> 5, c4 = (idx & 31) * 4;
            float4 v = *(const float4*)(ea + (size_t)(e0 + r) * DD + c4);
            __half2* d = (__half2*)(EAs + r * 136 + c4);
            d[0] = __floats2half2_rn(v.x, v.y);
            d[1] = __floats2half2_rn(v.z, v.w);
        }
#pragma unroll
        for (int j = 0; j < 16; j++) {
            int idx = tid + j * 256;
            int i = idx >> 5, k4 = (idx & 31) * 4;
            float4 v = *(const float4*)(w1 + (size_t)i * DD + k4);
            W1T[(k4 + 0) * 136 + i] = __float2half_rn(v.x);
            W1T[(k4 + 1) * 136 + i] = __float2half_rn(v.y);
            W1T[(k4 + 2) * 136 + i] = __float2half_rn(v.z);
            W1T[(k4 + 3) * 136 + i] = __float2half_rn(v.w);
        }
        if (tid < 128) b1s[tid] = b1[tid];
        __syncthreads();

        const int w = tid >> 5, lane = tid & 31;
        const int wE = w >> 1, wO = w & 1;
        const int g = lane >> 2, tg = lane & 3;
        const int er0 = wE * 32;
        const int ob = wO * 64;

        const unsigned* EA32 = (const unsigned*)EAs;
        const unsigned* W132 = (const unsigned*)W1T;

        float cacc[2][8][4];
#pragma unroll
        for (int a = 0; a < 2; a++)
#pragma unroll
            for (int bq = 0; bq < 8; bq++)
#pragma unroll
                for (int q = 0; q < 4; q++) cacc[a][bq][q] = 0.0f;

#pragma unroll
        for (int c = 0; c < 8; c++) {
            const int colu = c * 8 + tg;
            unsigned a0[4], a1[4];
            a0[0] = EA32[(er0 + g) * 68 + colu];
            a0[1] = EA32[(er0 + 8 + g) * 68 + colu];
            a0[2] = EA32[(er0 + g) * 68 + colu + 4];
            a0[3] = EA32[(er0 + 8 + g) * 68 + colu + 4];
            a1[0] = EA32[(er0 + 16 + g) * 68 + colu];
            a1[1] = EA32[(er0 + 24 + g) * 68 + colu];
            a1[2] = EA32[(er0 + 16 + g) * 68 + colu + 4];
            a1[3] = EA32[(er0 + 24 + g) * 68 + colu + 4];
#pragma unroll
            for (int nt = 0; nt < 8; nt++) {
                const int ro = ob + nt * 8 + g;
                unsigned B0 = W132[ro * 68 + colu];
                unsigned B1 = W132[ro * 68 + colu + 4];
                MMA_F16(cacc[0][nt], a0, B0, B1);
                MMA_F16(cacc[1][nt], a1, B0, B1);
            }
        }

#pragma unroll
        for (int mt = 0; mt < 2; mt++) {
            int r0 = e0 + er0 + mt * 16 + g;
            int r1 = r0 + 8;
#pragma unroll
            for (int nt = 0; nt < 8; nt++) {
                int col = ob + nt * 8 + tg * 2;
                float ba = b1s[col], bb = b1s[col + 1];
                float2 v0 = make_float2(fmaxf(cacc[mt][nt][0] + ba, 0.0f),
                                        fmaxf(cacc[mt][nt][1] + bb, 0.0f));
                float2 v1 = make_float2(fmaxf(cacc[mt][nt][2] + ba, 0.0f),
                                        fmaxf(cacc[mt][nt][3] + bb, 0.0f));
                *(float2*)(g_h + (size_t)r0 * DD + col) = v0;
                *(float2*)(g_h + (size_t)r1 * DD + col) = v1;
            }
        }
    } else {
        int i = (b - 386) * 256 + tid;
        int stride = INIT_ZBLK * 256;
        for (int idx = i; idx < N_NODES * DD; idx += stride) g_seg[idx] = 0.0f;
        for (int idx = i; idx < N_NODES + 16; idx += stride) g_cnt[idx] = 0;
    }
}

// ---------------- K_fused: KB phase -> grid barrier -> KC phase -------------

#define B_ROW_BYTES 144
#define B_SUB_BYTES (128 * B_ROW_BYTES)
#define B_TILE_BYTES (2 * B_SUB_BYTES)
#define XS_OFF  0
#define HS_OFF  (128 * 132 * 4)
#define BS_OFF  (2 * 128 * 132 * 4)
#define MISC_OFF (BS_OFF + 2 * B_TILE_BYTES)
#define SMEM_KB (MISC_OFF + 1024)

// KC-phase smem layout (aliases the KB region; used only after the barrier)
#define KCF_XH 0
#define KCF_RT (64 * 136 * 2)
#define KCF_BI (KCF_RT + 128 * 136 * 2)
#define KCF_SG (KCF_BI + 512)
#define KCF_CN (KCF_SG + 64 * 128 * 4)

__global__ __launch_bounds__(256) void k_fused(
    const float* __restrict__ x, const void* __restrict__ ei,
    const float* __restrict__ root, const float* __restrict__ bias,
    float* __restrict__ out)
{
    extern __shared__ char sm[];
    float* Xs  = (float*)(sm + XS_OFF);
    float* Hs  = (float*)(sm + HS_OFF);
    char*  BsC = sm + BS_OFF;
    int* s_src = (int*)(sm + MISC_OFF);
    int* s_dst = s_src + 128;

    const int tid = threadIdx.x;
    const int bid = blockIdx.x;

    const int g0 = (int)(((long long)bid * NCH_TOT) / KB_GRID);
    const int g1 = (int)(((long long)(bid + 1) * NCH_TOT) / KB_GRID);

    const int w = tid >> 5, lane = tid & 31;
    const int wE = w >> 1, wO = w & 1;
    const int g = lane >> 2, tg = lane & 3;
    const int er0 = wE * 32;
    const int ob = wO * 64;

    float cacc[2][8][4];

#define ZERO_CACC()                                                             \
    do {                                                                        \
        _Pragma("unroll") for (int _a = 0; _a < 2; _a++)                        \
        _Pragma("unroll") for (int _b = 0; _b < 8; _b++)                        \
        _Pragma("unroll") for (int _q = 0; _q < 4; _q++) cacc[_a][_b][_q] = 0.0f;\
    } while (0)

#define SCATTER_CACC()                                                          \
    do {                                                                        \
        _Pragma("unroll") for (int _mt = 0; _mt < 2; _mt++) {                   \
            int _rl = er0 + _mt * 16 + g;                                       \
            int _d0 = s_dst[_rl];                                               \
            int _d1 = s_dst[_rl + 8];                                           \
            _Pragma("unroll") for (int _nt = 0; _nt < 8; _nt++) {               \
                int _cb = ob + _nt * 8 + tg * 2;                                \
                atomicAdd(g_seg + (size_t)_d0 * DD + _cb,     cacc[_mt][_nt][0]);\
                atomicAdd(g_seg + (size_t)_d0 * DD + _cb + 1, cacc[_mt][_nt][1]);\
                atomicAdd(g_seg + (size_t)_d1 * DD + _cb,     cacc[_mt][_nt][2]);\
                atomicAdd(g_seg + (size_t)_d1 * DD + _cb + 1, cacc[_mt][_nt][3]);\
            }                                                                   \
        }                                                                       \
    } while (0)

#define LOAD_TILE(_tile)                                                        \
    do {                                                                        \
        int _eb = (_tile) * 128;                                                \
        if (tid < 128) {                                                        \
            int _s = load_idx(ei, _eb + tid);                                   \
            int _d = load_idx(ei, N_EDGES + _eb + tid);                         \
            s_src[tid] = _s;                                                    \
            s_dst[tid] = _d;                                                    \
            if ((_tile) * NCH_PT >= g0) atomicAdd(&g_cnt[_d], 1);               \
        }                                                                       \
        __syncthreads();                                                        \
        _Pragma("unroll") for (int _j = 0; _j < 16; _j++) {                     \
            int _idx = tid + _j * 256;                                          \
            int _r = _idx >> 5, _c4 = _idx & 31;                                \
            *(float4*)(Xs + _r * 132 + _c4 * 4) =                               \
                *(const float4*)(x + (size_t)s_src[_r] * DD + _c4 * 4);         \
            *(float4*)(Hs + _r * 132 + _c4 * 4) =                               \
                *(const float4*)(g_h + (size_t)(_eb + _r) * DD + _c4 * 4);      \
        }                                                                       \
    } while (0)

#define ISSUE_B(_gg)                                                            \
    do {                                                                        \
        int _l = (_gg) - ((_gg) / NCH_PT) * NCH_PT;                             \
        const __half* _bsrc = g_w2h + (size_t)_l * 16384;                       \
        char* _bd = BsC + ((_gg) & 1) * B_TILE_BYTES;                           \
        _Pragma("unroll") for (int _j = 0; _j < 8; _j++) {                      \
            int _idx = tid + _j * 256;                                          \
            int _ih = _idx >> 10, _rem = _idx & 1023;                           \
            int _r = _rem >> 3, _ch = _rem & 7;                                 \
            cp_async16(_bd + _ih * B_SUB_BYTES + _r * B_ROW_BYTES + _ch * 16,   \
                       _bsrc + _idx * 8);                                       \
        }                                                                       \
    } while (0)

    int cur_tile = g0 / NCH_PT;
    LOAD_TILE(cur_tile);
    ZERO_CACC();

#pragma unroll
    for (int p = 0; p < 2; p++) {
        int gg = g0 + p;
        if (gg < g1) ISSUE_B(gg);
        CP_COMMIT();
    }

    const float* hrow = Hs + (er0 + g) * 132;
    const float* xrow = Xs + (er0 + g) * 132;

    for (int gi = g0; gi < g1; gi++) {
        const int tile = gi / NCH_PT;
        const int l = gi - tile * NCH_PT;

        if (tile != cur_tile) {
            SCATTER_CACC();
            __syncthreads();
            LOAD_TILE(tile);
            ZERO_CACC();
            cur_tile = tile;
        }

        CP_WAIT1();
        __syncthreads();

        const char* bsm = BsC + (gi & 1) * B_TILE_BYTES;

        float h0, h1, h2, h3;
        if (l < 128) {
            h0 = hrow[l]; h1 = hrow[8 * 132 + l];
            h2 = hrow[16 * 132 + l]; h3 = hrow[24 * 132 + l];
        } else {
            h0 = h1 = h2 = h3 = 1.0f;
        }

#pragma unroll
        for (int ih = 0; ih < 2; ih++) {
            const int ibase = ih * 64;
            const char* bsmi = bsm + ih * B_SUB_BYTES;
#pragma unroll
            for (int s = 0; s < 4; s++) {
                const int iA = ibase + s * 16 + tg * 2;
                unsigned a0[4], a1[4];
                {
                    const float* r0 = xrow;
                    const float* r1 = xrow + 8 * 132;
                    float2 p0 = *(const float2*)(r0 + iA);
                    float2 p1 = *(const float2*)(r1 + iA);
                    float2 p2 = *(const float2*)(r0 + iA + 8);
                    float2 p3 = *(const float2*)(r1 + iA + 8);
                    a0[0] = pack_h2(h0 * p0.x, h0 * p0.y);
                    a0[1] = pack_h2(h1 * p1.x, h1 * p1.y);
                    a0[2] = pack_h2(h0 * p2.x, h0 * p2.y);
                    a0[3] = pack_h2(h1 * p3.x, h1 * p3.y);
                }
                {
                    const float* r0 = xrow + 16 * 132;
                    const float* r1 = xrow + 24 * 132;
                    float2 p0 = *(const float2*)(r0 + iA);
                    float2 p1 = *(const float2*)(r1 + iA);
                    float2 p2 = *(const float2*)(r0 + iA + 8);
                    float2 p3 = *(const float2*)(r1 + iA + 8);
                    a1[0] = pack_h2(h2 * p0.x, h2 * p0.y);
                    a1[1] = pack_h2(h3 * p1.x, h3 * p1.y);
                    a1[2] = pack_h2(h2 * p2.x, h2 * p2.y);
                    a1[3] = pack_h2(h3 * p3.x, h3 * p3.y);
                }
                const char* bp = bsmi + (ob + g) * B_ROW_BYTES + s * 32 + tg * 4;
#pragma unroll
                for (int nt = 0; nt < 8; nt++) {
                    const char* bq = bp + nt * 8 * B_ROW_BYTES;
                    unsigned B0 = *(const unsigned*)(bq);
                    unsigned B1 = *(const unsigned*)(bq + 16);
                    MMA_F16(cacc[0][nt], a0, B0, B1);
                    MMA_F16(cacc[1][nt], a1, B0, B1);
                }
            }
        }

        __syncthreads();
        int gg = gi + 2;
        if (gg < g1) ISSUE_B(gg);
        CP_COMMIT();
    }

    SCATTER_CACC();

    // ---- grid-wide barrier (all 148 CTAs co-resident: 1 CTA/SM) ----
    __threadfence();
    __syncthreads();
    if (tid == 0) {
        atomicAdd(&g_bar, 1u);
        unsigned v; long long it = 0;
        do {
            v = *((volatile unsigned*)&g_bar);
            if (++it > 200000000LL) asm volatile("trap;");
        } while (v < (unsigned)KB_GRID);
    }
    __syncthreads();
    __threadfence();

    // ---- KC phase: out = x + gelu(seg/cnt + x@root + bias) ----
    {
        __half* XH  = (__half*)(sm + KCF_XH);   // [64][136]
        __half* RT  = (__half*)(sm + KCF_RT);   // [128][136]
        float*  bs  = (float*)(sm + KCF_BI);
        float*  SGs = (float*)(sm + KCF_SG);    // [64][128]
        int*    CNs = (int*)(sm + KCF_CN);      // [64]

        // stage root^T + bias once (tile-invariant)
#pragma unroll
        for (int j = 0; j < 16; j++) {
            int idx = tid + j * 256;
            int i = idx >> 5, o4 = (idx & 31) * 4;
            float4 v = *(const float4*)(root + (size_t)i * DD + o4);
            RT[(o4 + 0) * 136 + i] = __float2half_rn(v.x);
            RT[(o4 + 1) * 136 + i] = __float2half_rn(v.y);
            RT[(o4 + 2) * 136 + i] = __float2half_rn(v.z);
            RT[(o4 + 3) * 136 + i] = __float2half_rn(v.w);
        }
        if (tid < 128) bs[tid] = bias[tid];

        const int wE2 = w >> 1, wO2 = w & 1;
        const int er2 = wE2 * 16;
        const int ob2 = wO2 * 64;

        for (int t = bid; t < KC_TILES; t += KB_GRID) {
            const int n0 = t * 64;

            // prefetch seg tile + cnt (L2-hot: just written by this grid)
#pragma unroll
            for (int j = 0; j < 8; j++) {
                int idx = tid + j * 256;
                int r = idx >> 5, c4 = (idx & 31) * 4;
                if (n0 + r < N_NODES)
                    cp_async16(SGs + r * 128 + c4,
                               g_seg + (size_t)(n0 + r) * DD + c4);
            }
            if (tid < 16) {
                if (n0 + tid * 4 < N_NODES)
                    cp_async16(CNs + tid * 4, g_cnt + n0 + tid * 4);
            }
            CP_COMMIT();

#pragma unroll
            for (int j = 0; j < 8; j++) {
                int idx = tid + j * 256;
                int r = idx >> 5, c4 = (idx & 31) * 4;
                float4 v = make_float4(0.f, 0.f, 0.f, 0.f);
                if (n0 + r < N_NODES)
                    v = *(const float4*)(x + (size_t)(n0 + r) * DD + c4);
                __half2* d = (__half2*)(XH + r * 136 + c4);
                d[0] = __floats2half2_rn(v.x, v.y);
                d[1] = __floats2half2_rn(v.z, v.w);
            }
            __syncthreads();

            const unsigned* XH32 = (const unsigned*)XH;
            const unsigned* RT32 = (const unsigned*)RT;

            float kacc[8][4];
#pragma unroll
            for (int bq = 0; bq < 8; bq++)
#pragma unroll
                for (int q = 0; q < 4; q++) kacc[bq][q] = 0.0f;

#pragma unroll
            for (int c = 0; c < 8; c++) {
                const int colu = c * 8 + tg;
                unsigned a0[4];
                a0[0] = XH32[(er2 + g) * 68 + colu];
                a0[1] = XH32[(er2 + 8 + g) * 68 + colu];
                a0[2] = XH32[(er2 + g) * 68 + colu + 4];
                a0[3] = XH32[(er2 + 8 + g) * 68 + colu + 4];
#pragma unroll
                for (int nt = 0; nt < 8; nt++) {
                    const int ro = ob2 + nt * 8 + g;
                    unsigned B0 = RT32[ro * 68 + colu];
                    unsigned B1 = RT32[ro * 68 + colu + 4];
                    MMA_F16(kacc[nt], a0, B0, B1);
                }
            }

            CP_WAIT0();
            __syncthreads();

            {
                int rl0 = er2 + g;
                int rl1 = rl0 + 8;
                int r0 = n0 + rl0, r1 = n0 + rl1;
                float invc0 = 0.f, invc1 = 0.f;
                if (r0 < N_NODES) invc0 = 1.0f / fmaxf((float)CNs[rl0], 1.0f);
                if (r1 < N_NODES) invc1 = 1.0f / fmaxf((float)CNs[rl1], 1.0f);
#pragma unroll
                for (int nt = 0; nt < 8; nt++) {
                    int col = ob2 + nt * 8 + tg * 2;
                    float ba = bs[col], bb = bs[col + 1];
                    if (r0 < N_NODES) {
                        float2 sg = *(const float2*)(SGs + rl0 * 128 + col);
                        float2 xv = *(const float2*)(x + (size_t)r0 * DD + col);
                        float va = kacc[nt][0] + ba + sg.x * invc0;
                        float vb = kacc[nt][1] + bb + sg.y * invc0;
                        float ga = 0.5f * va * (1.0f + erff(va * 0.70710678118654752f));
                        float gb = 0.5f * vb * (1.0f + erff(vb * 0.70710678118654752f));
                        float2 o2;
                        o2.x = xv.x + ga;
                        o2.y = xv.y + gb;
                        *(float2*)(out + (size_t)r0 * DD + col) = o2;
                    }
                    if (r1 < N_NODES) {
                        float2 sg = *(const float2*)(SGs + rl1 * 128 + col);
                        float2 xv = *(const float2*)(x + (size_t)r1 * DD + col);
                        float va = kacc[nt][2] + ba + sg.x * invc1;
                        float vb = kacc[nt][3] + bb + sg.y * invc1;
                        float ga = 0.5f * va * (1.0f + erff(va * 0.70710678118654752f));
                        float gb = 0.5f * vb * (1.0f + erff(vb * 0.70710678118654752f));
                        float2 o2;
                        o2.x = xv.x + ga;
                        o2.y = xv.y + gb;
                        *(float2*)(out + (size_t)r1 * DD + col) = o2;
                    }
                }
            }
            __syncthreads();   // XH/SGs reuse safety for next tile
        }
    }
}

// ---------------- launch ----------------

extern "C" void kernel_launch(void* const* d_in, const int* in_sizes, int n_in,
                              void* d_out, int out_size) {
    const float* x    = (const float*)d_in[0];
    const void*  ei   = (const void*)d_in[1];
    const float* ea   = (const float*)d_in[2];
    const float* w1   = (const float*)d_in[3];
    const float* b1   = (const float*)d_in[4];
    const float* w2   = (const float*)d_in[5];
    const float* b2   = (const float*)d_in[6];
    const float* root = (const float*)d_in[7];
    const float* bias = (const float*)d_in[8];
    float*       out  = (float*)d_out;

    cudaFuncSetAttribute(k_pre,   cudaFuncAttributeMaxDynamicSharedMemorySize, SMEM_PRE);
    cudaFuncSetAttribute(k_fused, cudaFuncAttributeMaxDynamicSharedMemorySize, SMEM_KB);

    k_pre<<<PRE_GRID, 256, SMEM_PRE>>>(w2, b2, ei, ea, w1, b1);
    k_fused<<<KB_GRID, 256, SMEM_KB>>>(x, ei, root, bias, out);
}

// round 16
// speedup vs baseline: 1.0669x; 1.0669x over previous
#include <cuda_runtime.h>
#include <cuda_fp16.h>
#include <cstdint>

// ---------------------------------------------------------------------------
// NNConv fused pipeline, fp16 mma.sync (legacy tensor path).
//   K_pre:  w2 transpose (258 blk) + KA edge-MLP (128 blk)
//           + RB = x@root + bias (157 blk, independent of KB!) + zeroing (160)
//   KB:     msg GEMM, K=128 chunks, 2-slot/2-barrier, balanced 148 CTAs
//           (96% tensor-bound, byte-identical to R13 champion)
//   K_post: out = x + gelu(seg/cnt + rb)  -- pure element-wise stream
// ---------------------------------------------------------------------------

#define N_NODES 10000
#define N_EDGES 16384
#define DD      128
#define W2HN    ((DD + 1) * 16384)
#define NTILES  (N_EDGES / 128)
#define NCH_PT  129
#define NCH_TOT (NTILES * NCH_PT)        // 16512
#define KB_GRID 148
#define RB_TILES ((N_NODES + 63) / 64)   // 157

__device__ float  g_h[N_EDGES * DD];
__device__ __half g_w2h[W2HN];           // [k][ih][o][il]
__device__ float  g_seg[N_NODES * DD];
__device__ float  g_rb[N_NODES * DD];    // x@root + bias (pre-KB)
__device__ int    g_cnt[N_NODES + 16];
__device__ int    g_is64;

// ---------------- helpers ----------------

__device__ __forceinline__ int load_idx(const void* ei, int pos) {
    if (g_is64) return (int)((const long long*)ei)[pos];
    return ((const int*)ei)[pos];
}

__device__ __forceinline__ void cp_async16(void* smem_dst, const void* gsrc) {
    unsigned saddr = (unsigned)__cvta_generic_to_shared(smem_dst);
    asm volatile("cp.async.cg.shared.global [%0], [%1], 16;\n" ::"r"(saddr), "l"(gsrc));
}
#define CP_COMMIT() asm volatile("cp.async.commit_group;\n")
#define CP_WAIT1()  asm volatile("cp.async.wait_group 1;\n")

#define MMA_F16(C, A, B0, B1)                                                   \
    asm volatile(                                                               \
        "mma.sync.aligned.m16n8k16.row.col.f32.f16.f16.f32 "                    \
        "{%0,%1,%2,%3}, {%4,%5,%6,%7}, {%8,%9}, {%0,%1,%2,%3};\n"               \
        : "+f"((C)[0]), "+f"((C)[1]), "+f"((C)[2]), "+f"((C)[3])                \
        : "r"((A)[0]), "r"((A)[1]), "r"((A)[2]), "r"((A)[3]),                   \
          "r"((B0)), "r"((B1)))

__device__ __forceinline__ unsigned pack_h2(float a, float b) {
    unsigned u;
    asm("cvt.rn.f16x2.f32 %0, %2, %1;" : "=r"(u) : "f"(a), "f"(b));
    return u;
}

// ---------------- K_pre: transpose(258) + KA(128) + RB(157) + zero(160) -----

#define INIT_ZBLK 160
#define PRE_GRID  (258 + 128 + RB_TILES + INIT_ZBLK)   // 703

#define KA_EA_OFF  0
#define KA_W1_OFF  (128 * 136 * 2)
#define KA_B1_OFF  (2 * 128 * 136 * 2)
#define SMEM_PRE   (KA_B1_OFF + 512 + 256)

// RB role smem layout (within SMEM_PRE)
#define RB_XH_OFF  0
#define RB_RT_OFF  (64 * 136 * 2)
#define RB_BI_OFF  (RB_RT_OFF + 128 * 136 * 2)

__global__ __launch_bounds__(256) void k_pre(
    const float* __restrict__ w2, const float* __restrict__ b2,
    const void* __restrict__ ei,
    const float* __restrict__ ea, const float* __restrict__ w1,
    const float* __restrict__ b1,
    const float* __restrict__ x, const float* __restrict__ root,
    const float* __restrict__ bias)
{
    extern __shared__ char smP[];
    const int b = blockIdx.x;
    const int tid = threadIdx.x;

    if (b < 258) {
        if (b == 0 && tid < 32) {
            const int* e32 = (const int*)ei;
            int nz = 0;
            for (int i = tid; i < 2048; i += 32) nz |= e32[2 * i + 1];
            unsigned any = __ballot_sync(0xffffffffu, nz != 0);
            if (tid == 0) g_is64 = (any == 0u) ? 1 : 0;
        }
        __half* ts = (__half*)smP;              // [64][136]
        const int k = b >> 1, ih = b & 1;
        const float* src = ((k < DD) ? (w2 + (size_t)k * 16384) : b2) + ih * 64 * 128;
#pragma unroll
        for (int j = 0; j < 8; j++) {
            int idx = tid + j * 256;
            int ii = idx >> 5, o4 = (idx & 31) * 4;
            float4 v = *(const float4*)(src + ii * 128 + o4);
            __half2* d = (__half2*)(ts + ii * 136 + o4);
            d[0] = __floats2half2_rn(v.x, v.y);
            d[1] = __floats2half2_rn(v.z, v.w);
        }
        __syncthreads();
#pragma unroll
        for (int j = 0; j < 4; j++) {
            int idx = tid + j * 256;
            int o = idx >> 3, il8 = (idx & 7) * 8;
            __half tmp[8];
#pragma unroll
            for (int q = 0; q < 8; q++) tmp[q] = ts[(il8 + q) * 136 + o];
            *(uint4*)(g_w2h + (size_t)k * 16384 + ih * 8192 + o * 64 + il8) =
                *(uint4*)tmp;
        }
    } else if (b < 386) {
        // ---- KA: h = relu(ea @ w1 + b1) ----
        __half* EAs = (__half*)(smP + KA_EA_OFF);
        __half* W1T = (__half*)(smP + KA_W1_OFF);
        float*  b1s = (float*)(smP + KA_B1_OFF);
        const int e0 = (b - 258) * 128;

#pragma unroll
        for (int j = 0; j < 16; j++) {
            int idx = tid + j * 256;
            int r = idx >> 5, c4 = (idx & 31) * 4;
            float4 v = *(const float4*)(ea + (size_t)(e0 + r) * DD + c4);
            __half2* d = (__half2*)(EAs + r * 136 + c4);
            d[0] = __floats2half2_rn(v.x, v.y);
            d[1] = __floats2half2_rn(v.z, v.w);
        }
#pragma unroll
        for (int j = 0; j < 16; j++) {
            int idx = tid + j * 256;
            int i = idx >> 5, k4 = (idx & 31) * 4;
            float4 v = *(const float4*)(w1 + (size_t)i * DD + k4);
            W1T[(k4 + 0) * 136 + i] = __float2half_rn(v.x);
            W1T[(k4 + 1) * 136 + i] = __float2half_rn(v.y);
            W1T[(k4 + 2) * 136 + i] = __float2half_rn(v.z);
            W1T[(k4 + 3) * 136 + i] = __float2half_rn(v.w);
        }
        if (tid < 128) b1s[tid] = b1[tid];
        __syncthreads();

        const int w = tid >> 5, lane = tid & 31;
        const int wE = w >> 1, wO = w & 1;
        const int g = lane >> 2, tg = lane & 3;
        const int er0 = wE * 32;
        const int ob = wO * 64;

        const unsigned* EA32 = (const unsigned*)EAs;
        const unsigned* W132 = (const unsigned*)W1T;

        float cacc[2][8][4];
#pragma unroll
        for (int a = 0; a < 2; a++)
#pragma unroll
            for (int bq = 0; bq < 8; bq++)
#pragma unroll
                for (int q = 0; q < 4; q++) cacc[a][bq][q] = 0.0f;

#pragma unroll
        for (int c = 0; c < 8; c++) {
            const int colu = c * 8 + tg;
            unsigned a0[4], a1[4];
            a0[0] = EA32[(er0 + g) * 68 + colu];
            a0[1] = EA32[(er0 + 8 + g) * 68 + colu];
            a0[2] = EA32[(er0 + g) * 68 + colu + 4];
            a0[3] = EA32[(er0 + 8 + g) * 68 + colu + 4];
            a1[0] = EA32[(er0 + 16 + g) * 68 + colu];
            a1[1] = EA32[(er0 + 24 + g) * 68 + colu];
            a1[2] = EA32[(er0 + 16 + g) * 68 + colu + 4];
            a1[3] = EA32[(er0 + 24 + g) * 68 + colu + 4];
#pragma unroll
            for (int nt = 0; nt < 8; nt++) {
                const int ro = ob + nt * 8 + g;
                unsigned B0 = W132[ro * 68 + colu];
                unsigned B1 = W132[ro * 68 + colu + 4];
                MMA_F16(cacc[0][nt], a0, B0, B1);
                MMA_F16(cacc[1][nt], a1, B0, B1);
            }
        }

#pragma unroll
        for (int mt = 0; mt < 2; mt++) {
            int r0 = e0 + er0 + mt * 16 + g;
            int r1 = r0 + 8;
#pragma unroll
            for (int nt = 0; nt < 8; nt++) {
                int col = ob + nt * 8 + tg * 2;
                float ba = b1s[col], bb = b1s[col + 1];
                float2 v0 = make_float2(fmaxf(cacc[mt][nt][0] + ba, 0.0f),
                                        fmaxf(cacc[mt][nt][1] + bb, 0.0f));
                float2 v1 = make_float2(fmaxf(cacc[mt][nt][2] + ba, 0.0f),
                                        fmaxf(cacc[mt][nt][3] + bb, 0.0f));
                *(float2*)(g_h + (size_t)r0 * DD + col) = v0;
                *(float2*)(g_h + (size_t)r1 * DD + col) = v1;
            }
        }
    } else if (b < 386 + RB_TILES) {
        // ---- RB: rb = x @ root + bias (independent of KB) ----
        __half* XH = (__half*)(smP + RB_XH_OFF);   // [64][136]
        __half* RT = (__half*)(smP + RB_RT_OFF);   // [128][136]
        float*  bs = (float*)(smP + RB_BI_OFF);
        const int n0 = (b - 386) * 64;

#pragma unroll
        for (int j = 0; j < 8; j++) {
            int idx = tid + j * 256;
            int r = idx >> 5, c4 = (idx & 31) * 4;
            float4 v = make_float4(0.f, 0.f, 0.f, 0.f);
            if (n0 + r < N_NODES)
                v = *(const float4*)(x + (size_t)(n0 + r) * DD + c4);
            __half2* d = (__half2*)(XH + r * 136 + c4);
            d[0] = __floats2half2_rn(v.x, v.y);
            d[1] = __floats2half2_rn(v.z, v.w);
        }
#pragma unroll
        for (int j = 0; j < 16; j++) {
            int idx = tid + j * 256;
            int i = idx >> 5, o4 = (idx & 31) * 4;
            float4 v = *(const float4*)(root + (size_t)i * DD + o4);
            RT[(o4 + 0) * 136 + i] = __float2half_rn(v.x);
            RT[(o4 + 1) * 136 + i] = __float2half_rn(v.y);
            RT[(o4 + 2) * 136 + i] = __float2half_rn(v.z);
            RT[(o4 + 3) * 136 + i] = __float2half_rn(v.w);
        }
        if (tid < 128) bs[tid] = bias[tid];
        __syncthreads();

        const int w = tid >> 5, lane = tid & 31;
        const int wE = w >> 1, wO = w & 1;
        const int g = lane >> 2, tg = lane & 3;
        const int er0 = wE * 16;
        const int ob = wO * 64;

        const unsigned* XH32 = (const unsigned*)XH;
        const unsigned* RT32 = (const unsigned*)RT;

        float kacc[8][4];
#pragma unroll
        for (int bq = 0; bq < 8; bq++)
#pragma unroll
            for (int q = 0; q < 4; q++) kacc[bq][q] = 0.0f;

#pragma unroll
        for (int c = 0; c < 8; c++) {
            const int colu = c * 8 + tg;
            unsigned a0[4];
            a0[0] = XH32[(er0 + g) * 68 + colu];
            a0[1] = XH32[(er0 + 8 + g) * 68 + colu];
            a0[2] = XH32[(er0 + g) * 68 + colu + 4];
            a0[3] = XH32[(er0 + 8 + g) * 68 + colu + 4];
#pragma unroll
            for (int nt = 0; nt < 8; nt++) {
                const int ro = ob + nt * 8 + g;
                unsigned B0 = RT32[ro * 68 + colu];
                unsigned B1 = RT32[ro * 68 + colu + 4];
                MMA_F16(kacc[nt], a0, B0, B1);
            }
        }

        {
            int rl0 = er0 + g, rl1 = rl0 + 8;
            int r0 = n0 + rl0, r1 = n0 + rl1;
#pragma unroll
            for (int nt = 0; nt < 8; nt++) {
                int col = ob + nt * 8 + tg * 2;
                float ba = bs[col], bb = bs[col + 1];
                if (r0 < N_NODES) {
                    float2 v = make_float2(kacc[nt][0] + ba, kacc[nt][1] + bb);
                    *(float2*)(g_rb + (size_t)r0 * DD + col) = v;
                }
                if (r1 < N_NODES) {
                    float2 v = make_float2(kacc[nt][2] + ba, kacc[nt][3] + bb);
                    *(float2*)(g_rb + (size_t)r1 * DD + col) = v;
                }
            }
        }
    } else {
        int i = (b - 386 - RB_TILES) * 256 + tid;
        int stride = INIT_ZBLK * 256;
        for (int idx = i; idx < N_NODES * DD; idx += stride) g_seg[idx] = 0.0f;
        for (int idx = i; idx < N_NODES + 16; idx += stride) g_cnt[idx] = 0;
    }
}

// ---------------- KB: K=128 chunks, 2-slot/2-barrier (R13 champion, frozen) -

#define B_ROW_BYTES 144
#define B_SUB_BYTES (128 * B_ROW_BYTES)
#define B_TILE_BYTES (2 * B_SUB_BYTES)
#define XS_OFF  0
#define HS_OFF  (128 * 132 * 4)
#define BS_OFF  (2 * 128 * 132 * 4)
#define MISC_OFF (BS_OFF + 2 * B_TILE_BYTES)
#define SMEM_KB (MISC_OFF + 1024)

__global__ __launch_bounds__(256) void k_msg(
    const float* __restrict__ x, const void* __restrict__ ei)
{
    extern __shared__ char sm[];
    float* Xs  = (float*)(sm + XS_OFF);
    float* Hs  = (float*)(sm + HS_OFF);
    char*  BsC = sm + BS_OFF;
    int* s_src = (int*)(sm + MISC_OFF);
    int* s_dst = s_src + 128;

    const int tid = threadIdx.x;
    const int bid = blockIdx.x;

    const int g0 = (int)(((long long)bid * NCH_TOT) / KB_GRID);
    const int g1 = (int)(((long long)(bid + 1) * NCH_TOT) / KB_GRID);

    const int w = tid >> 5, lane = tid & 31;
    const int wE = w >> 1, wO = w & 1;
    const int g = lane >> 2, tg = lane & 3;
    const int er0 = wE * 32;
    const int ob = wO * 64;

    float cacc[2][8][4];

#define ZERO_CACC()                                                             \
    do {                                                                        \
        _Pragma("unroll") for (int _a = 0; _a < 2; _a++)                        \
        _Pragma("unroll") for (int _b = 0; _b < 8; _b++)                        \
        _Pragma("unroll") for (int _q = 0; _q < 4; _q++) cacc[_a][_b][_q] = 0.0f;\
    } while (0)

#define SCATTER_CACC()                                                          \
    do {                                                                        \
        _Pragma("unroll") for (int _mt = 0; _mt < 2; _mt++) {                   \
            int _rl = er0 + _mt * 16 + g;                                       \
            int _d0 = s_dst[_rl];                                               \
            int _d1 = s_dst[_rl + 8];                                           \
            _Pragma("unroll") for (int _nt = 0; _nt < 8; _nt++) {               \
                int _cb = ob + _nt * 8 + tg * 2;                                \
                atomicAdd(g_seg + (size_t)_d0 * DD + _cb,     cacc[_mt][_nt][0]);\
                atomicAdd(g_seg + (size_t)_d0 * DD + _cb + 1, cacc[_mt][_nt][1]);\
                atomicAdd(g_seg + (size_t)_d1 * DD + _cb,     cacc[_mt][_nt][2]);\
                atomicAdd(g_seg + (size_t)_d1 * DD + _cb + 1, cacc[_mt][_nt][3]);\
            }                                                                   \
        }                                                                       \
    } while (0)

#define LOAD_TILE(_tile)                                                        \
    do {                                                                        \
        int _eb = (_tile) * 128;                                                \
        if (tid < 128) {                                                        \
            int _s = load_idx(ei, _eb + tid);                                   \
            int _d = load_idx(ei, N_EDGES + _eb + tid);                         \
            s_src[tid] = _s;                                                    \
            s_dst[tid] = _d;                                                    \
            if ((_tile) * NCH_PT >= g0) atomicAdd(&g_cnt[_d], 1);               \
        }                                                                       \
        __syncthreads();                                                        \
        _Pragma("unroll") for (int _j = 0; _j < 16; _j++) {                     \
            int _idx = tid + _j * 256;                                          \
            int _r = _idx >> 5, _c4 = _idx & 31;                                \
            *(float4*)(Xs + _r * 132 + _c4 * 4) =                               \
                *(const float4*)(x + (size_t)s_src[_r] * DD + _c4 * 4);         \
            *(float4*)(Hs + _r * 132 + _c4 * 4) =                               \
                *(const float4*)(g_h + (size_t)(_eb + _r) * DD + _c4 * 4);      \
        }                                                                       \
    } while (0)

#define ISSUE_B(_gg)                                                            \
    do {                                                                        \
        int _l = (_gg) - ((_gg) / NCH_PT) * NCH_PT;                             \
        const __half* _bsrc = g_w2h + (size_t)_l * 16384;                       \
        char* _bd = BsC + ((_gg) & 1) * B_TILE_BYTES;                           \
        _Pragma("unroll") for (int _j = 0; _j < 8; _j++) {                      \
            int _idx = tid + _j * 256;                                          \
            int _ih = _idx >> 10, _rem = _idx & 1023;                           \
            int _r = _rem >> 3, _ch = _rem & 7;                                 \
            cp_async16(_bd + _ih * B_SUB_BYTES + _r * B_ROW_BYTES + _ch * 16,   \
                       _bsrc + _idx * 8);                                       \
        }                                                                       \
    } while (0)

    int cur_tile = g0 / NCH_PT;
    LOAD_TILE(cur_tile);
    ZERO_CACC();

#pragma unroll
    for (int p = 0; p < 2; p++) {
        int gg = g0 + p;
        if (gg < g1) ISSUE_B(gg);
        CP_COMMIT();
    }

    const float* hrow = Hs + (er0 + g) * 132;
    const float* xrow = Xs + (er0 + g) * 132;

    for (int gi = g0; gi < g1; gi++) {
        const int tile = gi / NCH_PT;
        const int l = gi - tile * NCH_PT;

        if (tile != cur_tile) {
            SCATTER_CACC();
            __syncthreads();
            LOAD_TILE(tile);
            ZERO_CACC();
            cur_tile = tile;
        }

        CP_WAIT1();
        __syncthreads();

        const char* bsm = BsC + (gi & 1) * B_TILE_BYTES;

        float h0, h1, h2, h3;
        if (l < 128) {
            h0 = hrow[l]; h1 = hrow[8 * 132 + l];
            h2 = hrow[16 * 132 + l]; h3 = hrow[24 * 132 + l];
        } else {
            h0 = h1 = h2 = h3 = 1.0f;
        }

#pragma unroll
        for (int ih = 0; ih < 2; ih++) {
            const int ibase = ih * 64;
            const char* bsmi = bsm + ih * B_SUB_BYTES;
#pragma unroll
            for (int s = 0; s < 4; s++) {
                const int iA = ibase + s * 16 + tg * 2;
                unsigned a0[4], a1[4];
                {
                    const float* r0 = xrow;
                    const float* r1 = xrow + 8 * 132;
                    float2 p0 = *(const float2*)(r0 + iA);
                    float2 p1 = *(const float2*)(r1 + iA);
                    float2 p2 = *(const float2*)(r0 + iA + 8);
                    float2 p3 = *(const float2*)(r1 + iA + 8);
                    a0[0] = pack_h2(h0 * p0.x, h0 * p0.y);
                    a0[1] = pack_h2(h1 * p1.x, h1 * p1.y);
                    a0[2] = pack_h2(h0 * p2.x, h0 * p2.y);
                    a0[3] = pack_h2(h1 * p3.x, h1 * p3.y);
                }
                {
                    const float* r0 = xrow + 16 * 132;
                    const float* r1 = xrow + 24 * 132;
                    float2 p0 = *(const float2*)(r0 + iA);
                    float2 p1 = *(const float2*)(r1 + iA);
                    float2 p2 = *(const float2*)(r0 + iA + 8);
                    float2 p3 = *(const float2*)(r1 + iA + 8);
                    a1[0] = pack_h2(h2 * p0.x, h2 * p0.y);
                    a1[1] = pack_h2(h3 * p1.x, h3 * p1.y);
                    a1[2] = pack_h2(h2 * p2.x, h2 * p2.y);
                    a1[3] = pack_h2(h3 * p3.x, h3 * p3.y);
                }
                const char* bp = bsmi + (ob + g) * B_ROW_BYTES + s * 32 + tg * 4;
#pragma unroll
                for (int nt = 0; nt < 8; nt++) {
                    const char* bq = bp + nt * 8 * B_ROW_BYTES;
                    unsigned B0 = *(const unsigned*)(bq);
                    unsigned B1 = *(const unsigned*)(bq + 16);
                    MMA_F16(cacc[0][nt], a0, B0, B1);
                    MMA_F16(cacc[1][nt], a1, B0, B1);
                }
            }
        }

        __syncthreads();
        int gg = gi + 2;
        if (gg < g1) ISSUE_B(gg);
        CP_COMMIT();
    }

    SCATTER_CACC();
}

// ---------------- K_post: out = x + gelu(seg/cnt + rb), element-wise --------

#define POST_GRID ((N_NODES * (DD / 4) + 255) / 256)   // 1250

__global__ __launch_bounds__(256) void k_post(
    const float* __restrict__ x, float* __restrict__ out)
{
    int i = blockIdx.x * 256 + threadIdx.x;            // float4 index
    if (i >= N_NODES * (DD / 4)) return;
    int node = i >> 5;
    float invc = 1.0f / fmaxf((float)g_cnt[node], 1.0f);
    float4 sg = *(const float4*)(g_seg + (size_t)i * 4);
    float4 rb = *(const float4*)(g_rb + (size_t)i * 4);
    float4 xv = *(const float4*)(x + (size_t)i * 4);
    float4 o;
    {
        float v = rb.x + sg.x * invc;
        o.x = xv.x + 0.5f * v * (1.0f + erff(v * 0.70710678118654752f));
    }
    {
        float v = rb.y + sg.y * invc;
        o.y = xv.y + 0.5f * v * (1.0f + erff(v * 0.70710678118654752f));
    }
    {
        float v = rb.z + sg.z * invc;
        o.z = xv.z + 0.5f * v * (1.0f + erff(v * 0.70710678118654752f));
    }
    {
        float v = rb.w + sg.w * invc;
        o.w = xv.w + 0.5f * v * (1.0f + erff(v * 0.70710678118654752f));
    }
    *(float4*)(out + (size_t)i * 4) = o;
}

// ---------------- launch ----------------

extern "C" void kernel_launch(void* const* d_in, const int* in_sizes, int n_in,
                              void* d_out, int out_size) {
    const float* x    = (const float*)d_in[0];
    const void*  ei   = (const void*)d_in[1];
    const float* ea   = (const float*)d_in[2];
    const float* w1   = (const float*)d_in[3];
    const float* b1   = (const float*)d_in[4];
    const float* w2   = (const float*)d_in[5];
    const float* b2   = (const float*)d_in[6];
    const float* root = (const float*)d_in[7];
    const float* bias = (const float*)d_in[8];
    float*       out  = (float*)d_out;

    cudaFuncSetAttribute(k_pre, cudaFuncAttributeMaxDynamicSharedMemorySize, SMEM_PRE);
    cudaFuncSetAttribute(k_msg, cudaFuncAttributeMaxDynamicSharedMemorySize, SMEM_KB);

    k_pre<<<PRE_GRID, 256, SMEM_PRE>>>(w2, b2, ei, ea, w1, b1, x, root, bias);
    k_msg<<<KB_GRID, 256, SMEM_KB>>>(x, ei);
    k_post<<<POST_GRID, 256>>>(x, out);
}

// round 17
// speedup vs baseline: 1.0735x; 1.0062x over previous
#include <cuda_runtime.h>
#include <cuda_fp16.h>
#include <cstdint>

// ---------------------------------------------------------------------------
// NNConv fused pipeline, fp16 mma.sync (legacy tensor path) + PDL overlap.
//   K_pre:  w2 transpose (258) + KA edge-MLP (128) + RB = x@root+bias (157)
//           + zeroing (160); triggers dependents at block completion.
//   KB:     msg GEMM (R13/R16 champion body, frozen). PDL: independent
//           prologue (idx + Xs) before griddepcontrol.wait.
//   K_post: out = x + gelu(seg/cnt + rb), element-wise; PDL.
// ---------------------------------------------------------------------------

#define N_NODES 10000
#define N_EDGES 16384
#define DD      128
#define W2HN    ((DD + 1) * 16384)
#define NTILES  (N_EDGES / 128)
#define NCH_PT  129
#define NCH_TOT (NTILES * NCH_PT)        // 16512
#define KB_GRID 148
#define RB_TILES ((N_NODES + 63) / 64)   // 157

__device__ float  g_h[N_EDGES * DD];
__device__ __half g_w2h[W2HN];           // [k][ih][o][il]
__device__ float  g_seg[N_NODES * DD];
__device__ float  g_rb[N_NODES * DD];    // x@root + bias (pre-KB)
__device__ int    g_cnt[N_NODES + 16];
__device__ int    g_is64;

// ---------------- helpers ----------------

#define GDC_WAIT()   asm volatile("griddepcontrol.wait;" ::: "memory")
#define GDC_LAUNCH() asm volatile("griddepcontrol.launch_dependents;" ::: "memory")

__device__ __forceinline__ int load_idx(const void* ei, int pos) {
    if (g_is64) return (int)((const long long*)ei)[pos];
    return ((const int*)ei)[pos];
}

__device__ __forceinline__ void cp_async16(void* smem_dst, const void* gsrc) {
    unsigned saddr = (unsigned)__cvta_generic_to_shared(smem_dst);
    asm volatile("cp.async.cg.shared.global [%0], [%1], 16;\n" ::"r"(saddr), "l"(gsrc));
}
#define CP_COMMIT() asm volatile("cp.async.commit_group;\n")
#define CP_WAIT1()  asm volatile("cp.async.wait_group 1;\n")

#define MMA_F16(C, A, B0, B1)                                                   \
    asm volatile(                                                               \
        "mma.sync.aligned.m16n8k16.row.col.f32.f16.f16.f32 "                    \
        "{%0,%1,%2,%3}, {%4,%5,%6,%7}, {%8,%9}, {%0,%1,%2,%3};\n"               \
        : "+f"((C)[0]), "+f"((C)[1]), "+f"((C)[2]), "+f"((C)[3])                \
        : "r"((A)[0]), "r"((A)[1]), "r"((A)[2]), "r"((A)[3]),                   \
          "r"((B0)), "r"((B1)))

__device__ __forceinline__ unsigned pack_h2(float a, float b) {
    unsigned u;
    asm("cvt.rn.f16x2.f32 %0, %2, %1;" : "=r"(u) : "f"(a), "f"(b));
    return u;
}

// ---------------- K_pre: transpose(258) + KA(128) + RB(157) + zero(160) -----

#define INIT_ZBLK 160
#define PRE_GRID  (258 + 128 + RB_TILES + INIT_ZBLK)   // 703

#define KA_EA_OFF  0
#define KA_W1_OFF  (128 * 136 * 2)
#define KA_B1_OFF  (2 * 128 * 136 * 2)
#define SMEM_PRE   (KA_B1_OFF + 512 + 256)

#define RB_XH_OFF  0
#define RB_RT_OFF  (64 * 136 * 2)
#define RB_BI_OFF  (RB_RT_OFF + 128 * 136 * 2)

__global__ __launch_bounds__(256) void k_pre(
    const float* __restrict__ w2, const float* __restrict__ b2,
    const void* __restrict__ ei,
    const float* __restrict__ ea, const float* __restrict__ w1,
    const float* __restrict__ b1,
    const float* __restrict__ x, const float* __restrict__ root,
    const float* __restrict__ bias)
{
    extern __shared__ char smP[];
    const int b = blockIdx.x;
    const int tid = threadIdx.x;

    if (b < 258) {
        if (b == 0 && tid < 32) {
            const int* e32 = (const int*)ei;
            int nz = 0;
            for (int i = tid; i < 2048; i += 32) nz |= e32[2 * i + 1];
            unsigned any = __ballot_sync(0xffffffffu, nz != 0);
            if (tid == 0) g_is64 = (any == 0u) ? 1 : 0;
        }
        __half* ts = (__half*)smP;              // [64][136]
        const int k = b >> 1, ih = b & 1;
        const float* src = ((k < DD) ? (w2 + (size_t)k * 16384) : b2) + ih * 64 * 128;
#pragma unroll
        for (int j = 0; j < 8; j++) {
            int idx = tid + j * 256;
            int ii = idx >> 5, o4 = (idx & 31) * 4;
            float4 v = *(const float4*)(src + ii * 128 + o4);
            __half2* d = (__half2*)(ts + ii * 136 + o4);
            d[0] = __floats2half2_rn(v.x, v.y);
            d[1] = __floats2half2_rn(v.z, v.w);
        }
        __syncthreads();
#pragma unroll
        for (int j = 0; j < 4; j++) {
            int idx = tid + j * 256;
            int o = idx >> 3, il8 = (idx & 7) * 8;
            __half tmp[8];
#pragma unroll
            for (int q = 0; q < 8; q++) tmp[q] = ts[(il8 + q) * 136 + o];
            *(uint4*)(g_w2h + (size_t)k * 16384 + ih * 8192 + o * 64 + il8) =
                *(uint4*)tmp;
        }
        GDC_LAUNCH();
    } else if (b < 386) {
        // ---- KA: h = relu(ea @ w1 + b1) ----
        __half* EAs = (__half*)(smP + KA_EA_OFF);
        __half* W1T = (__half*)(smP + KA_W1_OFF);
        float*  b1s = (float*)(smP + KA_B1_OFF);
        const int e0 = (b - 258) * 128;

#pragma unroll
        for (int j = 0; j < 16; j++) {
            int idx = tid + j * 256;
            int r = idx >> 5, c4 = (idx & 31) * 4;
            float4 v = *(const float4*)(ea + (size_t)(e0 + r) * DD + c4);
            __half2* d = (__half2*)(EAs + r * 136 + c4);
            d[0] = __floats2half2_rn(v.x, v.y);
            d[1] = __floats2half2_rn(v.z, v.w);
        }
#pragma unroll
        for (int j = 0; j < 16; j++) {
            int idx = tid + j * 256;
            int i = idx >> 5, k4 = (idx & 31) * 4;
            float4 v = *(const float4*)(w1 + (size_t)i * DD + k4);
            W1T[(k4 + 0) * 136 + i] = __float2half_rn(v.x);
            W1T[(k4 + 1) * 136 + i] = __float2half_rn(v.y);
            W1T[(k4 + 2) * 136 + i] = __float2half_rn(v.z);
            W1T[(k4 + 3) * 136 + i] = __float2half_rn(v.w);
        }
        if (tid < 128) b1s[tid] = b1[tid];
        __syncthreads();

        const int w = tid >> 5, lane = tid & 31;
        const int wE = w >> 1, wO = w & 1;
        const int g = lane >> 2, tg = lane & 3;
        const int er0 = wE * 32;
        const int ob = wO * 64;

        const unsigned* EA32 = (const unsigned*)EAs;
        const unsigned* W132 = (const unsigned*)W1T;

        float cacc[2][8][4];
#pragma unroll
        for (int a = 0; a < 2; a++)
#pragma unroll
            for (int bq = 0; bq < 8; bq++)
#pragma unroll
                for (int q = 0; q < 4; q++) cacc[a][bq][q] = 0.0f;

#pragma unroll
        for (int c = 0; c < 8; c++) {
            const int colu = c * 8 + tg;
            unsigned a0[4], a1[4];
            a0[0] = EA32[(er0 + g) * 68 + colu];
            a0[1] = EA32[(er0 + 8 + g) * 68 + colu];
            a0[2] = EA32[(er0 + g) * 68 + colu + 4];
            a0[3] = EA32[(er0 + 8 + g) * 68 + colu + 4];
            a1[0] = EA32[(er0 + 16 + g) * 68 + colu];
            a1[1] = EA32[(er0 + 24 + g) * 68 + colu];
            a1[2] = EA32[(er0 + 16 + g) * 68 + colu + 4];
            a1[3] = EA32[(er0 + 24 + g) * 68 + colu + 4];
#pragma unroll
            for (int nt = 0; nt < 8; nt++) {
                const int ro = ob + nt * 8 + g;
                unsigned B0 = W132[ro * 68 + colu];
                unsigned B1 = W132[ro * 68 + colu + 4];
                MMA_F16(cacc[0][nt], a0, B0, B1);
                MMA_F16(cacc[1][nt], a1, B0, B1);
            }
        }

#pragma unroll
        for (int mt = 0; mt < 2; mt++) {
            int r0 = e0 + er0 + mt * 16 + g;
            int r1 = r0 + 8;
#pragma unroll
            for (int nt = 0; nt < 8; nt++) {
                int col = ob + nt * 8 + tg * 2;
                float ba = b1s[col], bb = b1s[col + 1];
                float2 v0 = make_float2(fmaxf(cacc[mt][nt][0] + ba, 0.0f),
                                        fmaxf(cacc[mt][nt][1] + bb, 0.0f));
                float2 v1 = make_float2(fmaxf(cacc[mt][nt][2] + ba, 0.0f),
                                        fmaxf(cacc[mt][nt][3] + bb, 0.0f));
                *(float2*)(g_h + (size_t)r0 * DD + col) = v0;
                *(float2*)(g_h + (size_t)r1 * DD + col) = v1;
            }
        }
        GDC_LAUNCH();
    } else if (b < 386 + RB_TILES) {
        // ---- RB: rb = x @ root + bias ----
        __half* XH = (__half*)(smP + RB_XH_OFF);
        __half* RT = (__half*)(smP + RB_RT_OFF);
        float*  bs = (float*)(smP + RB_BI_OFF);
        const int n0 = (b - 386) * 64;

#pragma unroll
        for (int j = 0; j < 8; j++) {
            int idx = tid + j * 256;
            int r = idx >> 5, c4 = (idx & 31) * 4;
            float4 v = make_float4(0.f, 0.f, 0.f, 0.f);
            if (n0 + r < N_NODES)
                v = *(const float4*)(x + (size_t)(n0 + r) * DD + c4);
            __half2* d = (__half2*)(XH + r * 136 + c4);
            d[0] = __floats2half2_rn(v.x, v.y);
            d[1] = __floats2half2_rn(v.z, v.w);
        }
#pragma unroll
        for (int j = 0; j < 16; j++) {
            int idx = tid + j * 256;
            int i = idx >> 5, o4 = (idx & 31) * 4;
            float4 v = *(const float4*)(root + (size_t)i * DD + o4);
            RT[(o4 + 0) * 136 + i] = __float2half_rn(v.x);
            RT[(o4 + 1) * 136 + i] = __float2half_rn(v.y);
            RT[(o4 + 2) * 136 + i] = __float2half_rn(v.z);
            RT[(o4 + 3) * 136 + i] = __float2half_rn(v.w);
        }
        if (tid < 128) bs[tid] = bias[tid];
        __syncthreads();

        const int w = tid >> 5, lane = tid & 31;
        const int wE = w >> 1, wO = w & 1;
        const int g = lane >> 2, tg = lane & 3;
        const int er0 = wE * 16;
        const int ob = wO * 64;

        const unsigned* XH32 = (const unsigned*)XH;
        const unsigned* RT32 = (const unsigned*)RT;

        float kacc[8][4];
#pragma unroll
        for (int bq = 0; bq < 8; bq++)
#pragma unroll
            for (int q = 0; q < 4; q++) kacc[bq][q] = 0.0f;

#pragma unroll
        for (int c = 0; c < 8; c++) {
            const int colu = c * 8 + tg;
            unsigned a0[4];
            a0[0] = XH32[(er0 + g) * 68 + colu];
            a0[1] = XH32[(er0 + 8 + g) * 68 + colu];
            a0[2] = XH32[(er0 + g) * 68 + colu + 4];
            a0[3] = XH32[(er0 + 8 + g) * 68 + colu + 4];
#pragma unroll
            for (int nt = 0; nt < 8; nt++) {
                const int ro = ob + nt * 8 + g;
                unsigned B0 = RT32[ro * 68 + colu];
                unsigned B1 = RT32[ro * 68 + colu + 4];
                MMA_F16(kacc[nt], a0, B0, B1);
            }
        }

        {
            int rl0 = er0 + g, rl1 = rl0 + 8;
            int r0 = n0 + rl0, r1 = n0 + rl1;
#pragma unroll
            for (int nt = 0; nt < 8; nt++) {
                int col = ob + nt * 8 + tg * 2;
                float ba = bs[col], bb = bs[col + 1];
                if (r0 < N_NODES) {
                    float2 v = make_float2(kacc[nt][0] + ba, kacc[nt][1] + bb);
                    *(float2*)(g_rb + (size_t)r0 * DD + col) = v;
                }
                if (r1 < N_NODES) {
                    float2 v = make_float2(kacc[nt][2] + ba, kacc[nt][3] + bb);
                    *(float2*)(g_rb + (size_t)r1 * DD + col) = v;
                }
            }
        }
        GDC_LAUNCH();
    } else {
        int i = (b - 386 - RB_TILES) * 256 + tid;
        int stride = INIT_ZBLK * 256;
        for (int idx = i; idx < N_NODES * DD; idx += stride) g_seg[idx] = 0.0f;
        for (int idx = i; idx < N_NODES + 16; idx += stride) g_cnt[idx] = 0;
        GDC_LAUNCH();
    }
}

// ---------------- KB: K=128 chunks, 2-slot/2-barrier (frozen) + PDL ---------

#define B_ROW_BYTES 144
#define B_SUB_BYTES (128 * B_ROW_BYTES)
#define B_TILE_BYTES (2 * B_SUB_BYTES)
#define XS_OFF  0
#define HS_OFF  (128 * 132 * 4)
#define BS_OFF  (2 * 128 * 132 * 4)
#define MISC_OFF (BS_OFF + 2 * B_TILE_BYTES)
#define SMEM_KB (MISC_OFF + 1024)

__global__ __launch_bounds__(256) void k_msg(
    const float* __restrict__ x, const void* __restrict__ ei)
{
    extern __shared__ char sm[];
    float* Xs  = (float*)(sm + XS_OFF);
    float* Hs  = (float*)(sm + HS_OFF);
    char*  BsC = sm + BS_OFF;
    int* s_src = (int*)(sm + MISC_OFF);
    int* s_dst = s_src + 128;

    const int tid = threadIdx.x;
    const int bid = blockIdx.x;

    const int g0 = (int)(((long long)bid * NCH_TOT) / KB_GRID);
    const int g1 = (int)(((long long)(bid + 1) * NCH_TOT) / KB_GRID);

    const int w = tid >> 5, lane = tid & 31;
    const int wE = w >> 1, wO = w & 1;
    const int g = lane >> 2, tg = lane & 3;
    const int er0 = wE * 32;
    const int ob = wO * 64;

    float cacc[2][8][4];

#define ZERO_CACC()                                                             \
    do {                                                                        \
        _Pragma("unroll") for (int _a = 0; _a < 2; _a++)                        \
        _Pragma("unroll") for (int _b = 0; _b < 8; _b++)                        \
        _Pragma("unroll") for (int _q = 0; _q < 4; _q++) cacc[_a][_b][_q] = 0.0f;\
    } while (0)

#define SCATTER_CACC()                                                          \
    do {                                                                        \
        _Pragma("unroll") for (int _mt = 0; _mt < 2; _mt++) {                   \
            int _rl = er0 + _mt * 16 + g;                                       \
            int _d0 = s_dst[_rl];                                               \
            int _d1 = s_dst[_rl + 8];                                           \
            _Pragma("unroll") for (int _nt = 0; _nt < 8; _nt++) {               \
                int _cb = ob + _nt * 8 + tg * 2;                                \
                atomicAdd(g_seg + (size_t)_d0 * DD + _cb,     cacc[_mt][_nt][0]);\
                atomicAdd(g_seg + (size_t)_d0 * DD + _cb + 1, cacc[_mt][_nt][1]);\
                atomicAdd(g_seg + (size_t)_d1 * DD + _cb,     cacc[_mt][_nt][2]);\
                atomicAdd(g_seg + (size_t)_d1 * DD + _cb + 1, cacc[_mt][_nt][3]);\
            }                                                                   \
        }                                                                       \
    } while (0)

#define LOAD_TILE(_tile)                                                        \
    do {                                                                        \
        int _eb = (_tile) * 128;                                                \
        if (tid < 128) {                                                        \
            int _s = load_idx(ei, _eb + tid);                                   \
            int _d = load_idx(ei, N_EDGES + _eb + tid);                         \
            s_src[tid] = _s;                                                    \
            s_dst[tid] = _d;                                                    \
            if ((_tile) * NCH_PT >= g0) atomicAdd(&g_cnt[_d], 1);               \
        }                                                                       \
        __syncthreads();                                                        \
        _Pragma("unroll") for (int _j = 0; _j < 16; _j++) {                     \
            int _idx = tid + _j * 256;                                          \
            int _r = _idx >> 5, _c4 = _idx & 31;                                \
            *(float4*)(Xs + _r * 132 + _c4 * 4) =                               \
                *(const float4*)(x + (size_t)s_src[_r] * DD + _c4 * 4);         \
            *(float4*)(Hs + _r * 132 + _c4 * 4) =                               \
                *(const float4*)(g_h + (size_t)(_eb + _r) * DD + _c4 * 4);      \
        }                                                                       \
    } while (0)

#define ISSUE_B(_gg)                                                            \
    do {                                                                        \
        int _l = (_gg) - ((_gg) / NCH_PT) * NCH_PT;                             \
        const __half* _bsrc = g_w2h + (size_t)_l * 16384;                       \
        char* _bd = BsC + ((_gg) & 1) * B_TILE_BYTES;                           \
        _Pragma("unroll") for (int _j = 0; _j < 8; _j++) {                      \
            int _idx = tid + _j * 256;                                          \
            int _ih = _idx >> 10, _rem = _idx & 1023;                           \
            int _r = _rem >> 3, _ch = _rem & 7;                                 \
            cp_async16(_bd + _ih * B_SUB_BYTES + _r * B_ROW_BYTES + _ch * 16,   \
                       _bsrc + _idx * 8);                                       \
        }                                                                       \
    } while (0)

    int cur_tile = g0 / NCH_PT;

    // --- PDL prologue: work independent of k_pre outputs ---
    // NOTE: load_idx reads g_is64 which is set by k_pre (block 0) of THIS
    // launch sequence, but also by every prior graph replay; to stay strictly
    // correct on the very first run we defer index decode until after wait.
    GDC_WAIT();

    LOAD_TILE(cur_tile);
    ZERO_CACC();

#pragma unroll
    for (int p = 0; p < 2; p++) {
        int gg = g0 + p;
        if (gg < g1) ISSUE_B(gg);
        CP_COMMIT();
    }

    const float* hrow = Hs + (er0 + g) * 132;
    const float* xrow = Xs + (er0 + g) * 132;

    for (int gi = g0; gi < g1; gi++) {
        const int tile = gi / NCH_PT;
        const int l = gi - tile * NCH_PT;

        if (tile != cur_tile) {
            SCATTER_CACC();
            __syncthreads();
            LOAD_TILE(tile);
            ZERO_CACC();
            cur_tile = tile;
        }

        CP_WAIT1();
        __syncthreads();

        const char* bsm = BsC + (gi & 1) * B_TILE_BYTES;

        float h0, h1, h2, h3;
        if (l < 128) {
            h0 = hrow[l]; h1 = hrow[8 * 132 + l];
            h2 = hrow[16 * 132 + l]; h3 = hrow[24 * 132 + l];
        } else {
            h0 = h1 = h2 = h3 = 1.0f;
        }

#pragma unroll
        for (int ih = 0; ih < 2; ih++) {
            const int ibase = ih * 64;
            const char* bsmi = bsm + ih * B_SUB_BYTES;
#pragma unroll
            for (int s = 0; s < 4; s++) {
                const int iA = ibase + s * 16 + tg * 2;
                unsigned a0[4], a1[4];
                {
                    const float* r0 = xrow;
                    const float* r1 = xrow + 8 * 132;
                    float2 p0 = *(const float2*)(r0 + iA);
                    float2 p1 = *(const float2*)(r1 + iA);
                    float2 p2 = *(const float2*)(r0 + iA + 8);
                    float2 p3 = *(const float2*)(r1 + iA + 8);
                    a0[0] = pack_h2(h0 * p0.x, h0 * p0.y);
                    a0[1] = pack_h2(h1 * p1.x, h1 * p1.y);
                    a0[2] = pack_h2(h0 * p2.x, h0 * p2.y);
                    a0[3] = pack_h2(h1 * p3.x, h1 * p3.y);
                }
                {
                    const float* r0 = xrow + 16 * 132;
                    const float* r1 = xrow + 24 * 132;
                    float2 p0 = *(const float2*)(r0 + iA);
                    float2 p1 = *(const float2*)(r1 + iA);
                    float2 p2 = *(const float2*)(r0 + iA + 8);
                    float2 p3 = *(const float2*)(r1 + iA + 8);
                    a1[0] = pack_h2(h2 * p0.x, h2 * p0.y);
                    a1[1] = pack_h2(h3 * p1.x, h3 * p1.y);
                    a1[2] = pack_h2(h2 * p2.x, h2 * p2.y);
                    a1[3] = pack_h2(h3 * p3.x, h3 * p3.y);
                }
                const char* bp = bsmi + (ob + g) * B_ROW_BYTES + s * 32 + tg * 4;
#pragma unroll
                for (int nt = 0; nt < 8; nt++) {
                    const char* bq = bp + nt * 8 * B_ROW_BYTES;
                    unsigned B0 = *(const unsigned*)(bq);
                    unsigned B1 = *(const unsigned*)(bq + 16);
                    MMA_F16(cacc[0][nt], a0, B0, B1);
                    MMA_F16(cacc[1][nt], a1, B0, B1);
                }
            }
        }

        __syncthreads();
        int gg = gi + 2;
        if (gg < g1) ISSUE_B(gg);
        CP_COMMIT();
    }

    SCATTER_CACC();
    GDC_LAUNCH();
}

// ---------------- K_post: out = x + gelu(seg/cnt + rb), element-wise + PDL --

#define POST_GRID ((N_NODES * (DD / 4) + 255) / 256)   // 1250

__global__ __launch_bounds__(256) void k_post(
    const float* __restrict__ x, float* __restrict__ out)
{
    GDC_WAIT();
    int i = blockIdx.x * 256 + threadIdx.x;            // float4 index
    if (i >= N_NODES * (DD / 4)) return;
    int node = i >> 5;
    float invc = 1.0f / fmaxf((float)g_cnt[node], 1.0f);
    float4 sg = *(const float4*)(g_seg + (size_t)i * 4);
    float4 rb = *(const float4*)(g_rb + (size_t)i * 4);
    float4 xv = *(const float4*)(x + (size_t)i * 4);
    float4 o;
    {
        float v = rb.x + sg.x * invc;
        o.x = xv.x + 0.5f * v * (1.0f + erff(v * 0.70710678118654752f));
    }
    {
        float v = rb.y + sg.y * invc;
        o.y = xv.y + 0.5f * v * (1.0f + erff(v * 0.70710678118654752f));
    }
    {
        float v = rb.z + sg.z * invc;
        o.z = xv.z + 0.5f * v * (1.0f + erff(v * 0.70710678118654752f));
    }
    {
        float v = rb.w + sg.w * invc;
        o.w = xv.w + 0.5f * v * (1.0f + erff(v * 0.70710678118654752f));
    }
    *(float4*)(out + (size_t)i * 4) = o;
}

// ---------------- launch ----------------

extern "C" void kernel_launch(void* const* d_in, const int* in_sizes, int n_in,
                              void* d_out, int out_size) {
    const float* x    = (const float*)d_in[0];
    const void*  ei   = (const void*)d_in[1];
    const float* ea   = (const float*)d_in[2];
    const float* w1   = (const float*)d_in[3];
    const float* b1   = (const float*)d_in[4];
    const float* w2   = (const float*)d_in[5];
    const float* b2   = (const float*)d_in[6];
    const float* root = (const float*)d_in[7];
    const float* bias = (const float*)d_in[8];
    float*       out  = (float*)d_out;

    cudaFuncSetAttribute(k_pre, cudaFuncAttributeMaxDynamicSharedMemorySize, SMEM_PRE);
    cudaFuncSetAttribute(k_msg, cudaFuncAttributeMaxDynamicSharedMemorySize, SMEM_KB);

    k_pre<<<PRE_GRID, 256, SMEM_PRE>>>(w2, b2, ei, ea, w1, b1, x, root, bias);

    // KB with programmatic dependent launch (overlaps launch with k_pre tail)
    {
        cudaLaunchConfig_t cfg = {};
        cfg.gridDim = dim3(KB_GRID, 1, 1);
        cfg.blockDim = dim3(256, 1, 1);
        cfg.dynamicSmemBytes = SMEM_KB;
        cudaLaunchAttribute attrs[1];
        attrs[0].id = cudaLaunchAttributeProgrammaticStreamSerialization;
        attrs[0].val.programmaticStreamSerializationAllowed = 1;
        cfg.attrs = attrs;
        cfg.numAttrs = 1;
        cudaLaunchKernelEx(&cfg, k_msg, x, (const void*)ei);
    }

    // k_post with PDL
    {
        cudaLaunchConfig_t cfg = {};
        cfg.gridDim = dim3(POST_GRID, 1, 1);
        cfg.blockDim = dim3(256, 1, 1);
        cfg.dynamicSmemBytes = 0;
        cudaLaunchAttribute attrs[1];
        attrs[0].id = cudaLaunchAttributeProgrammaticStreamSerialization;
        attrs[0].val.programmaticStreamSerializationAllowed = 1;
        cfg.attrs = attrs;
        cfg.numAttrs = 1;
        cudaLaunchKernelEx(&cfg, k_post, x, out);
    }
}